// round 11
// baseline (speedup 1.0000x reference)
#include <cuda_runtime.h>

#define HDIM   128
#define NSTEPS 60
#define SB     64
#define NTHR   512

typedef unsigned long long u64;
typedef ulonglong2 ull2;

__device__ __forceinline__ u64 pack2(float a, float b) {
    u64 r; asm("mov.b64 %0, {%1, %2};" : "=l"(r) : "f"(a), "f"(b)); return r;
}
__device__ __forceinline__ float2 unpack2(u64 v) {
    float2 r; asm("mov.b64 {%0, %1}, %2;" : "=f"(r.x), "=f"(r.y) : "l"(v)); return r;
}
__device__ __forceinline__ u64 ffma2(u64 a, u64 b, u64 c) {
    u64 d; asm("fma.rn.f32x2 %0, %1, %2, %3;" : "=l"(d) : "l"(a), "l"(b), "l"(c)); return d;
}
__device__ __forceinline__ u64 fmul2(u64 a, u64 b) {
    u64 d; asm("mul.rn.f32x2 %0, %1, %2;" : "=l"(d) : "l"(a), "l"(b)); return d;
}
__device__ __forceinline__ u64 fadd2(u64 a, u64 b) {
    u64 d; asm("add.rn.f32x2 %0, %1, %2;" : "=l"(d) : "l"(a), "l"(b)); return d;
}
__device__ __forceinline__ void silu_sd(float z, float& h, float& d) {
    float e = __expf(-z);
    float s = 1.0f / (1.0f + e);
    h = z * s;
    d = fmaf(h, 1.0f - s, s);
}
// pairwise silu (h and d packed like input)
__device__ __forceinline__ void silu2(u64 z, u64& h, u64& d) {
    float2 zf = unpack2(z);
    float h0, d0, h1, d1;
    silu_sd(zf.x, h0, d0);
    silu_sd(zf.y, h1, d1);
    h = pack2(h0, h1);
    d = pack2(d0, d1);
}

// FORWARD: acc[s] (f0) / acc[8+s] (f0+1), lanes = (even-k, odd-k) partial sums.
// z[f][s] = lanesum(acc).  ws = k-paired weights wpF[k2][f] (row len 128 u64).
// actA[k2][s]: u64 = (h[2k2][s], h[2k2+1][s]), row len 64 u64.
__device__ __forceinline__ void fwd_accum(const u64* __restrict__ ws,
                                          const u64* __restrict__ actA,
                                          int f0, int s0, u64 acc[16]) {
#pragma unroll 8
    for (int k2 = 0; k2 < 64; k2++) {
        ull2 w = *reinterpret_cast<const ull2*>(ws + k2 * 128 + f0);
        const u64* ar = actA + k2 * 64 + s0;
        ull2 a0 = *reinterpret_cast<const ull2*>(ar);
        ull2 a1 = *reinterpret_cast<const ull2*>(ar + 2);
        ull2 a2 = *reinterpret_cast<const ull2*>(ar + 4);
        ull2 a3 = *reinterpret_cast<const ull2*>(ar + 6);
        acc[0]  = ffma2(a0.x, w.x, acc[0]);   acc[1]  = ffma2(a0.y, w.x, acc[1]);
        acc[2]  = ffma2(a1.x, w.x, acc[2]);   acc[3]  = ffma2(a1.y, w.x, acc[3]);
        acc[4]  = ffma2(a2.x, w.x, acc[4]);   acc[5]  = ffma2(a2.y, w.x, acc[5]);
        acc[6]  = ffma2(a3.x, w.x, acc[6]);   acc[7]  = ffma2(a3.y, w.x, acc[7]);
        acc[8]  = ffma2(a0.x, w.y, acc[8]);   acc[9]  = ffma2(a0.y, w.y, acc[9]);
        acc[10] = ffma2(a1.x, w.y, acc[10]);  acc[11] = ffma2(a1.y, w.y, acc[11]);
        acc[12] = ffma2(a2.x, w.y, acc[12]);  acc[13] = ffma2(a2.y, w.y, acc[13]);
        acc[14] = ffma2(a3.x, w.y, acc[14]);  acc[15] = ffma2(a3.y, w.y, acc[15]);
    }
}

// BACKWARD: dz_in[j][s] = sum_t dz[t][s] * W[j][t].
// acc[j*4+q], lanes = samples (2*(q0+q), 2*(q0+q)+1).
// Weights: row fg of wpF; lane0 = W[f0][t], lane1 = W[f0+1][t].
// curS[t][q]: u64 = (dz[t][2q], dz[t][2q+1]), row len 32 u64.
__device__ __forceinline__ void bwd_accum(const u64* __restrict__ ws,
                                          const u64* __restrict__ curS,
                                          int fg, int q0, u64 acc[8]) {
#pragma unroll 8
    for (int t2 = 0; t2 < 64; t2++) {
        ull2 w = *reinterpret_cast<const ull2*>(ws + fg * 128 + 2 * t2);
        float2 we = unpack2(w.x);   // (W[f0][2t2],   W[f0+1][2t2])
        float2 wo = unpack2(w.y);   // (W[f0][2t2+1], W[f0+1][2t2+1])
        u64 w0e = pack2(we.x, we.x);
        u64 w1e = pack2(we.y, we.y);
        u64 w0o = pack2(wo.x, wo.x);
        u64 w1o = pack2(wo.y, wo.y);
        const u64* r0 = curS + (2 * t2) * 32 + q0;
        ull2 dA = *reinterpret_cast<const ull2*>(r0);        // t even, q0..q0+1
        ull2 dB = *reinterpret_cast<const ull2*>(r0 + 2);    // t even, q0+2..q0+3
        ull2 dC = *reinterpret_cast<const ull2*>(r0 + 32);   // t odd
        ull2 dD = *reinterpret_cast<const ull2*>(r0 + 34);
        acc[0] = ffma2(dA.x, w0e, acc[0]);  acc[0] = ffma2(dC.x, w0o, acc[0]);
        acc[1] = ffma2(dA.y, w0e, acc[1]);  acc[1] = ffma2(dC.y, w0o, acc[1]);
        acc[2] = ffma2(dB.x, w0e, acc[2]);  acc[2] = ffma2(dD.x, w0o, acc[2]);
        acc[3] = ffma2(dB.y, w0e, acc[3]);  acc[3] = ffma2(dD.y, w0o, acc[3]);
        acc[4] = ffma2(dA.x, w1e, acc[4]);  acc[4] = ffma2(dC.x, w1o, acc[4]);
        acc[5] = ffma2(dA.y, w1e, acc[5]);  acc[5] = ffma2(dC.y, w1o, acc[5]);
        acc[6] = ffma2(dB.x, w1e, acc[6]);  acc[6] = ffma2(dD.x, w1o, acc[6]);
        acc[7] = ffma2(dB.y, w1e, acc[7]);  acc[7] = ffma2(dD.y, w1o, acc[7]);
    }
}

// SMEM (u64 units): wp2 0 | wp3 8192 | wp4 16384 | act 24576 (4096)
//                   xsp 28672 (64) | w1s 28736 (128 u64 = 256 floats)
// total 28864 u64 = 230912 bytes
#define SMEM_BYTES 230912

__global__ void __launch_bounds__(NTHR, 1)
ebm_mcmc_kernel(const float* __restrict__ x0,
                const float* __restrict__ w1, const float* __restrict__ b1,
                const float* __restrict__ w2, const float* __restrict__ b2,
                const float* __restrict__ w3, const float* __restrict__ b3,
                const float* __restrict__ w4, const float* __restrict__ b4,
                const float* __restrict__ w5,
                const float* __restrict__ noise,
                float* __restrict__ out, int nsamp) {
    extern __shared__ u64 sm[];
    u64* wp2 = sm;
    u64* wp3 = sm + 8192;
    u64* wp4 = sm + 16384;
    u64* act = sm + 24576;                 // actA[64][64] fwd / curS[128][32] bwd
    u64* xsp = sm + 28672;                 // xsp[d*32 + s2]
    float* w1s = reinterpret_cast<float*>(sm + 28736);

    const int tid = threadIdx.x;
    const int fg  = tid >> 3;      // 0..63 (owns features f0, f0+1)
    const int sg  = tid & 7;       // 0..7  (owns samples s0..s0+7)
    const int f0  = fg << 1;
    const int s0  = sg << 3;
    const int q0  = sg << 2;       // first sample-pair index
    const int s0g = blockIdx.x * SB;

    // ---- build k-paired weights (once per block) ----
    for (int idx = tid; idx < 8192; idx += NTHR) {
        int k2 = idx >> 7, f = idx & 127;
        int g = k2 * 256 + f;
        wp2[idx] = pack2(w2[g], w2[g + 128]);
        wp3[idx] = pack2(w3[g], w3[g + 128]);
        wp4[idx] = pack2(w4[g], w4[g + 128]);
    }
    if (tid < 256) w1s[tid] = w1[tid];
    if (tid < 64) {
        int d = tid >> 5, s2 = tid & 31;
        size_t bx = (size_t)(s0g + 2 * s2) * 2 + d;
        xsp[tid] = pack2(x0[bx], x0[bx + 2]);
    }
    // per-thread weight/bias constants (live in registers all 60 steps)
    const float w1a0 = w1[f0],       w1a1 = w1[f0 + 1];
    const float w1b0 = w1[128 + f0], w1b1 = w1[128 + f0 + 1];
    const float b1c0 = b1[f0], b1c1 = b1[f0 + 1];
    const float b2c0 = b2[f0], b2c1 = b2[f0 + 1];
    const float b3c0 = b3[f0], b3c1 = b3[f0 + 1];
    const float b4c0 = b4[f0], b4c1 = b4[f0 + 1];
    const float w5c0 = w5[f0], w5c1 = w5[f0 + 1];
    __syncthreads();

    u64 sdp2[8], sdp3[8];          // silu' sample-paired, [j*4+q]

    // update-phase mapping
    const int jp = tid & 7;        // j-partition (16 j each)
    const int ug = tid >> 3;       // 0..63
    const int ud = ug >> 5;        // dim
    const int uq = ug & 31;        // s2

    for (int i = 0; i < NSTEPS; i++) {
        float eps = 10.0f * (1.0f - (float)i / 60.0f);
        float cn  = sqrtf(2.0f * eps) * 0.005f;

        float nz0 = 0.0f, nz1 = 0.0f;
        if (jp == 0) {
            size_t base = ((size_t)i * nsamp + s0g + 2 * uq) * 2 + ud;
            nz0 = noise[base];
            nz1 = noise[base + 2];
        }

        // ---- forward L1: h1 = silu(x @ W1 + b1), write feature-paired ----
        {
            u64 wa0 = pack2(w1a0, w1a0), wa1 = pack2(w1a1, w1a1);
            u64 wb0 = pack2(w1b0, w1b0), wb1 = pack2(w1b1, w1b1);
            u64 bb0 = pack2(b1c0, b1c0), bb1 = pack2(b1c1, b1c1);
            u64 hrow[8];
#pragma unroll
            for (int q = 0; q < 4; q++) {
                u64 xa = xsp[q0 + q], xb = xsp[32 + q0 + q];
                u64 z0 = ffma2(xa, wa0, ffma2(xb, wb0, bb0));   // f0, sample pair
                u64 z1 = ffma2(xa, wa1, ffma2(xb, wb1, bb1));   // f0+1
                u64 h0, h1, du;
                silu2(z0, h0, du);
                silu2(z1, h1, du);
                float2 a = unpack2(h0), b = unpack2(h1);
                hrow[2 * q]     = pack2(a.x, b.x);   // even sample, feature-paired
                hrow[2 * q + 1] = pack2(a.y, b.y);   // odd sample
            }
#pragma unroll
            for (int c = 0; c < 4; c++) {
                ull2 st; st.x = hrow[2 * c]; st.y = hrow[2 * c + 1];
                *reinterpret_cast<ull2*>(act + fg * 64 + s0 + 2 * c) = st;
            }
        }
        __syncthreads();

        // ---- forward L2 ----
        {
            u64 acc[16];
#pragma unroll
            for (int q = 0; q < 16; q++) acc[q] = 0ULL;
            fwd_accum(wp2, act, f0, s0, acc);
            u64 hrow[8];
#pragma unroll
            for (int q = 0; q < 4; q++) {
                float2 p0e = unpack2(acc[2 * q]);
                float2 p0o = unpack2(acc[2 * q + 1]);
                float2 p1e = unpack2(acc[8 + 2 * q]);
                float2 p1o = unpack2(acc[8 + 2 * q + 1]);
                float z0e = p0e.x + p0e.y + b2c0, z0o = p0o.x + p0o.y + b2c0;
                float z1e = p1e.x + p1e.y + b2c1, z1o = p1o.x + p1o.y + b2c1;
                float h0e, d0e, h0o, d0o, h1e, d1e, h1o, d1o;
                silu_sd(z0e, h0e, d0e);  silu_sd(z0o, h0o, d0o);
                silu_sd(z1e, h1e, d1e);  silu_sd(z1o, h1o, d1o);
                hrow[2 * q]     = pack2(h0e, h1e);
                hrow[2 * q + 1] = pack2(h0o, h1o);
                sdp2[q]     = pack2(d0e, d0o);
                sdp2[4 + q] = pack2(d1e, d1o);
            }
            __syncthreads();
#pragma unroll
            for (int c = 0; c < 4; c++) {
                ull2 st; st.x = hrow[2 * c]; st.y = hrow[2 * c + 1];
                *reinterpret_cast<ull2*>(act + fg * 64 + s0 + 2 * c) = st;
            }
        }
        __syncthreads();

        // ---- forward L3 ----
        {
            u64 acc[16];
#pragma unroll
            for (int q = 0; q < 16; q++) acc[q] = 0ULL;
            fwd_accum(wp3, act, f0, s0, acc);
            u64 hrow[8];
#pragma unroll
            for (int q = 0; q < 4; q++) {
                float2 p0e = unpack2(acc[2 * q]);
                float2 p0o = unpack2(acc[2 * q + 1]);
                float2 p1e = unpack2(acc[8 + 2 * q]);
                float2 p1o = unpack2(acc[8 + 2 * q + 1]);
                float z0e = p0e.x + p0e.y + b3c0, z0o = p0o.x + p0o.y + b3c0;
                float z1e = p1e.x + p1e.y + b3c1, z1o = p1o.x + p1o.y + b3c1;
                float h0e, d0e, h0o, d0o, h1e, d1e, h1o, d1o;
                silu_sd(z0e, h0e, d0e);  silu_sd(z0o, h0o, d0o);
                silu_sd(z1e, h1e, d1e);  silu_sd(z1o, h1o, d1o);
                hrow[2 * q]     = pack2(h0e, h1e);
                hrow[2 * q + 1] = pack2(h0o, h1o);
                sdp3[q]     = pack2(d0e, d0o);
                sdp3[4 + q] = pack2(d1e, d1o);
            }
            __syncthreads();
#pragma unroll
            for (int c = 0; c < 4; c++) {
                ull2 st; st.x = hrow[2 * c]; st.y = hrow[2 * c + 1];
                *reinterpret_cast<ull2*>(act + fg * 64 + s0 + 2 * c) = st;
            }
        }
        __syncthreads();

        // ---- forward L4 (h4 dead) + seed: dz4 = w5 .* silu'(z4), write sample-paired ----
        {
            u64 acc[16];
#pragma unroll
            for (int q = 0; q < 16; q++) acc[q] = 0ULL;
            fwd_accum(wp4, act, f0, s0, acc);
            u64 dz0[4], dz1[4];
#pragma unroll
            for (int q = 0; q < 4; q++) {
                float2 p0e = unpack2(acc[2 * q]);
                float2 p0o = unpack2(acc[2 * q + 1]);
                float2 p1e = unpack2(acc[8 + 2 * q]);
                float2 p1o = unpack2(acc[8 + 2 * q + 1]);
                float z0e = p0e.x + p0e.y + b4c0, z0o = p0o.x + p0o.y + b4c0;
                float z1e = p1e.x + p1e.y + b4c1, z1o = p1o.x + p1o.y + b4c1;
                float h, d0e, d0o, d1e, d1o;
                silu_sd(z0e, h, d0e);  silu_sd(z0o, h, d0o);
                silu_sd(z1e, h, d1e);  silu_sd(z1o, h, d1o);
                dz0[q] = pack2(w5c0 * d0e, w5c0 * d0o);   // f0 row, sample pair
                dz1[q] = pack2(w5c1 * d1e, w5c1 * d1o);   // f0+1
            }
            __syncthreads();   // all reads of h3 done; act becomes curS
            {
                ull2 s1v; s1v.x = dz0[0]; s1v.y = dz0[1];
                ull2 s2v; s2v.x = dz0[2]; s2v.y = dz0[3];
                *reinterpret_cast<ull2*>(act + f0 * 32 + q0)     = s1v;
                *reinterpret_cast<ull2*>(act + f0 * 32 + q0 + 2) = s2v;
                ull2 s3v; s3v.x = dz1[0]; s3v.y = dz1[1];
                ull2 s4v; s4v.x = dz1[2]; s4v.y = dz1[3];
                *reinterpret_cast<ull2*>(act + (f0 + 1) * 32 + q0)     = s3v;
                *reinterpret_cast<ull2*>(act + (f0 + 1) * 32 + q0 + 2) = s4v;
            }
        }
        __syncthreads();

        // ---- backward W4 -> dz3 ----
        {
            u64 acc[8];
#pragma unroll
            for (int q = 0; q < 8; q++) acc[q] = 0ULL;
            bwd_accum(wp4, act, fg, q0, acc);
            u64 dzv[8];
#pragma unroll
            for (int q = 0; q < 8; q++) dzv[q] = fmul2(acc[q], sdp3[q]);
            __syncthreads();
            {
                ull2 s1v; s1v.x = dzv[0]; s1v.y = dzv[1];
                ull2 s2v; s2v.x = dzv[2]; s2v.y = dzv[3];
                *reinterpret_cast<ull2*>(act + f0 * 32 + q0)     = s1v;
                *reinterpret_cast<ull2*>(act + f0 * 32 + q0 + 2) = s2v;
                ull2 s3v; s3v.x = dzv[4]; s3v.y = dzv[5];
                ull2 s4v; s4v.x = dzv[6]; s4v.y = dzv[7];
                *reinterpret_cast<ull2*>(act + (f0 + 1) * 32 + q0)     = s3v;
                *reinterpret_cast<ull2*>(act + (f0 + 1) * 32 + q0 + 2) = s4v;
            }
        }
        __syncthreads();

        // ---- backward W3 -> dz2 ----
        {
            u64 acc[8];
#pragma unroll
            for (int q = 0; q < 8; q++) acc[q] = 0ULL;
            bwd_accum(wp3, act, fg, q0, acc);
            u64 dzv[8];
#pragma unroll
            for (int q = 0; q < 8; q++) dzv[q] = fmul2(acc[q], sdp2[q]);
            __syncthreads();
            {
                ull2 s1v; s1v.x = dzv[0]; s1v.y = dzv[1];
                ull2 s2v; s2v.x = dzv[2]; s2v.y = dzv[3];
                *reinterpret_cast<ull2*>(act + f0 * 32 + q0)     = s1v;
                *reinterpret_cast<ull2*>(act + f0 * 32 + q0 + 2) = s2v;
                ull2 s3v; s3v.x = dzv[4]; s3v.y = dzv[5];
                ull2 s4v; s4v.x = dzv[6]; s4v.y = dzv[7];
                *reinterpret_cast<ull2*>(act + (f0 + 1) * 32 + q0)     = s3v;
                *reinterpret_cast<ull2*>(act + (f0 + 1) * 32 + q0 + 2) = s4v;
            }
        }
        __syncthreads();

        // ---- backward W2 -> dz1 (sd1 recomputed) ----
        {
            u64 acc[8];
#pragma unroll
            for (int q = 0; q < 8; q++) acc[q] = 0ULL;
            bwd_accum(wp2, act, fg, q0, acc);
            u64 wa0 = pack2(w1a0, w1a0), wa1 = pack2(w1a1, w1a1);
            u64 wb0 = pack2(w1b0, w1b0), wb1 = pack2(w1b1, w1b1);
            u64 bb0 = pack2(b1c0, b1c0), bb1 = pack2(b1c1, b1c1);
            u64 dzv[8];
#pragma unroll
            for (int q = 0; q < 4; q++) {
                u64 xa = xsp[q0 + q], xb = xsp[32 + q0 + q];
                u64 z0 = ffma2(xa, wa0, ffma2(xb, wb0, bb0));
                u64 z1 = ffma2(xa, wa1, ffma2(xb, wb1, bb1));
                u64 h, d0, d1;
                silu2(z0, h, d0);
                silu2(z1, h, d1);
                dzv[q]     = fmul2(acc[q],     d0);
                dzv[4 + q] = fmul2(acc[4 + q], d1);
            }
            __syncthreads();
            {
                ull2 s1v; s1v.x = dzv[0]; s1v.y = dzv[1];
                ull2 s2v; s2v.x = dzv[2]; s2v.y = dzv[3];
                *reinterpret_cast<ull2*>(act + f0 * 32 + q0)     = s1v;
                *reinterpret_cast<ull2*>(act + f0 * 32 + q0 + 2) = s2v;
                ull2 s3v; s3v.x = dzv[4]; s3v.y = dzv[5];
                ull2 s4v; s4v.x = dzv[6]; s4v.y = dzv[7];
                *reinterpret_cast<ull2*>(act + (f0 + 1) * 32 + q0)     = s3v;
                *reinterpret_cast<ull2*>(act + (f0 + 1) * 32 + q0 + 2) = s4v;
            }
        }
        __syncthreads();

        // ---- g = dz1 @ W1^T, clip, Langevin update ----
        {
            u64 g = 0ULL;
#pragma unroll
            for (int jj = 0; jj < 16; jj++) {
                int j = jp * 16 + jj;
                float w = w1s[ud * 128 + j];
                g = ffma2(act[j * 32 + uq], pack2(w, w), g);
            }
            g = fadd2(g, __shfl_down_sync(0xffffffffu, g, 4, 8));
            g = fadd2(g, __shfl_down_sync(0xffffffffu, g, 2, 8));
            g = fadd2(g, __shfl_down_sync(0xffffffffu, g, 1, 8));
            if (jp == 0) {
                float2 gv = unpack2(g);
                gv.x = fminf(fmaxf(gv.x, -0.03f), 0.03f);
                gv.y = fminf(fmaxf(gv.y, -0.03f), 0.03f);
                float2 xv = unpack2(xsp[ud * 32 + uq]);
                float ax = xv.x + cn * nz0;  ax += eps * gv.x;
                float ay = xv.y + cn * nz1;  ay += eps * gv.y;
                ax = fminf(fmaxf(ax, -2.43f), 3.05f);
                ay = fminf(fmaxf(ay, -2.43f), 3.05f);
                xsp[ud * 32 + uq] = pack2(ax, ay);
            }
        }
        __syncthreads();
    }

    // ---- write final x ----
    if (tid < 128) {
        int s = tid >> 1, d = tid & 1;
        float2 v = unpack2(xsp[d * 32 + (s >> 1)]);
        out[(size_t)(s0g + s) * 2 + d] = (s & 1) ? v.y : v.x;
    }
}

extern "C" void kernel_launch(void* const* d_in, const int* in_sizes, int n_in,
                              void* d_out, int out_size) {
    const float* x0    = (const float*)d_in[0];
    const float* w1    = (const float*)d_in[1];
    const float* b1    = (const float*)d_in[2];
    const float* w2    = (const float*)d_in[3];
    const float* b2    = (const float*)d_in[4];
    const float* w3    = (const float*)d_in[5];
    const float* b3    = (const float*)d_in[6];
    const float* w4    = (const float*)d_in[7];
    const float* b4    = (const float*)d_in[8];
    const float* w5    = (const float*)d_in[9];
    const float* noise = (const float*)d_in[11];
    float* out = (float*)d_out;

    int nsamp = in_sizes[0] / 2;
    cudaFuncSetAttribute(ebm_mcmc_kernel,
                         cudaFuncAttributeMaxDynamicSharedMemorySize, SMEM_BYTES);
    int nblocks = nsamp / SB;
    ebm_mcmc_kernel<<<nblocks, NTHR, SMEM_BYTES>>>(
        x0, w1, b1, w2, b2, w3, b3, w4, b4, w5, noise, out, nsamp);
}

// round 12
// speedup vs baseline: 1.5474x; 1.5474x over previous
#include <cuda_runtime.h>

#define HDIM   128
#define NSTEPS 60
#define SB     64
#define NTHR   512

typedef unsigned long long u64;
typedef ulonglong2 ull2;

__device__ __forceinline__ u64 pack2(float a, float b) {
    u64 r; asm("mov.b64 %0, {%1, %2};" : "=l"(r) : "f"(a), "f"(b)); return r;
}
__device__ __forceinline__ float2 unpack2(u64 v) {
    float2 r; asm("mov.b64 {%0, %1}, %2;" : "=f"(r.x), "=f"(r.y) : "l"(v)); return r;
}
__device__ __forceinline__ u64 ffma2(u64 a, u64 b, u64 c) {
    u64 d; asm("fma.rn.f32x2 %0, %1, %2, %3;" : "=l"(d) : "l"(a), "l"(b), "l"(c)); return d;
}
__device__ __forceinline__ u64 fmul2(u64 a, u64 b) {
    u64 d; asm("mul.rn.f32x2 %0, %1, %2;" : "=l"(d) : "l"(a), "l"(b)); return d;
}
__device__ __forceinline__ u64 fadd2(u64 a, u64 b) {
    u64 d; asm("add.rn.f32x2 %0, %1, %2;" : "=l"(d) : "l"(a), "l"(b)); return d;
}
__device__ __forceinline__ void silu_sd(float z, float& h, float& d) {
    float e = __expf(-z);
    float s = 1.0f / (1.0f + e);
    h = z * s;
    d = fmaf(h, 1.0f - s, s);
}
__device__ __forceinline__ void silu2(u64 z, u64& h, u64& d) {
    float2 zf = unpack2(z);
    float h0, d0, h1, d1;
    silu_sd(zf.x, h0, d0);
    silu_sd(zf.y, h1, d1);
    h = pack2(h0, h1);
    d = pack2(d0, d1);
}

// ---------------- swizzled layouts (all verified conflict-free) ----------------
// act fwd phase: row k2 (64 u64). logical 16B-chunk l = s>>1 (= 4sg+c for owner sg)
//   stored at phys chunk c*8+sg  ->  thread accesses u64 offsets {2sg + 16c}.
// act bwd phase: row t (32 u64 pairs). logical pair-chunk 2sg+c stored at c*8+sg
//   -> thread accesses u64 offsets {2sg, 16+2sg}.
// weights: row a (64 chunks). chunk c stored at c ^ (a&7).

// FORWARD: acc[s] (f0) / acc[8+s] (f0+1), lanes = (even-k, odd-k) partials.
__device__ __forceinline__ void fwd_accum(const u64* __restrict__ ws,
                                          const u64* __restrict__ actA,
                                          int fg, int sg, u64 acc[16]) {
    const int sofs = 2 * sg;
#pragma unroll 8
    for (int k2 = 0; k2 < 64; k2++) {
        ull2 w = *reinterpret_cast<const ull2*>(ws + k2 * 128 + 2 * (fg ^ (k2 & 7)));
        const u64* ar = actA + k2 * 64 + sofs;
        ull2 a0 = *reinterpret_cast<const ull2*>(ar);
        ull2 a1 = *reinterpret_cast<const ull2*>(ar + 16);
        ull2 a2 = *reinterpret_cast<const ull2*>(ar + 32);
        ull2 a3 = *reinterpret_cast<const ull2*>(ar + 48);
        acc[0]  = ffma2(a0.x, w.x, acc[0]);   acc[1]  = ffma2(a0.y, w.x, acc[1]);
        acc[2]  = ffma2(a1.x, w.x, acc[2]);   acc[3]  = ffma2(a1.y, w.x, acc[3]);
        acc[4]  = ffma2(a2.x, w.x, acc[4]);   acc[5]  = ffma2(a2.y, w.x, acc[5]);
        acc[6]  = ffma2(a3.x, w.x, acc[6]);   acc[7]  = ffma2(a3.y, w.x, acc[7]);
        acc[8]  = ffma2(a0.x, w.y, acc[8]);   acc[9]  = ffma2(a0.y, w.y, acc[9]);
        acc[10] = ffma2(a1.x, w.y, acc[10]);  acc[11] = ffma2(a1.y, w.y, acc[11]);
        acc[12] = ffma2(a2.x, w.y, acc[12]);  acc[13] = ffma2(a2.y, w.y, acc[13]);
        acc[14] = ffma2(a3.x, w.y, acc[14]);  acc[15] = ffma2(a3.y, w.y, acc[15]);
    }
}

// BACKWARD: acc[j*4+q] = dz_in for feature f0+j, sample-pair 4sg+q.
__device__ __forceinline__ void bwd_accum(const u64* __restrict__ ws,
                                          const u64* __restrict__ curS,
                                          int fg, int sg, u64 acc[8]) {
    const int m = fg & 7;
    const int sofs = 2 * sg;
#pragma unroll 8
    for (int t2 = 0; t2 < 64; t2++) {
        ull2 w = *reinterpret_cast<const ull2*>(ws + fg * 128 + 2 * (t2 ^ m));
        float2 we = unpack2(w.x);   // (W[f0][2t2],   W[f0+1][2t2])
        float2 wo = unpack2(w.y);   // (W[f0][2t2+1], W[f0+1][2t2+1])
        u64 w0e = pack2(we.x, we.x);
        u64 w1e = pack2(we.y, we.y);
        u64 w0o = pack2(wo.x, wo.x);
        u64 w1o = pack2(wo.y, wo.y);
        const u64* r0 = curS + (2 * t2) * 32 + sofs;
        ull2 dA = *reinterpret_cast<const ull2*>(r0);        // pairs 4sg, 4sg+1 (t even)
        ull2 dB = *reinterpret_cast<const ull2*>(r0 + 16);   // pairs 4sg+2, 4sg+3
        ull2 dC = *reinterpret_cast<const ull2*>(r0 + 32);   // t odd
        ull2 dD = *reinterpret_cast<const ull2*>(r0 + 48);
        acc[0] = ffma2(dA.x, w0e, acc[0]);  acc[0] = ffma2(dC.x, w0o, acc[0]);
        acc[1] = ffma2(dA.y, w0e, acc[1]);  acc[1] = ffma2(dC.y, w0o, acc[1]);
        acc[2] = ffma2(dB.x, w0e, acc[2]);  acc[2] = ffma2(dD.x, w0o, acc[2]);
        acc[3] = ffma2(dB.y, w0e, acc[3]);  acc[3] = ffma2(dD.y, w0o, acc[3]);
        acc[4] = ffma2(dA.x, w1e, acc[4]);  acc[4] = ffma2(dC.x, w1o, acc[4]);
        acc[5] = ffma2(dA.y, w1e, acc[5]);  acc[5] = ffma2(dC.y, w1o, acc[5]);
        acc[6] = ffma2(dB.x, w1e, acc[6]);  acc[6] = ffma2(dD.x, w1o, acc[6]);
        acc[7] = ffma2(dB.y, w1e, acc[7]);  acc[7] = ffma2(dD.y, w1o, acc[7]);
    }
}

// SMEM (u64 units): wp2 0 | wp3 8192 | wp4 16384 | act 24576 (4096)
//                   xsp 28672 (64) | w1s 28736 (128 u64 = 256 floats)
#define SMEM_BYTES 230912

__global__ void __launch_bounds__(NTHR, 1)
ebm_mcmc_kernel(const float* __restrict__ x0,
                const float* __restrict__ w1, const float* __restrict__ b1,
                const float* __restrict__ w2, const float* __restrict__ b2,
                const float* __restrict__ w3, const float* __restrict__ b3,
                const float* __restrict__ w4, const float* __restrict__ b4,
                const float* __restrict__ w5,
                const float* __restrict__ noise,
                float* __restrict__ out, int nsamp) {
    extern __shared__ u64 sm[];
    u64* wp2 = sm;
    u64* wp3 = sm + 8192;
    u64* wp4 = sm + 16384;
    u64* act = sm + 24576;
    u64* xsp = sm + 28672;
    float* w1s = reinterpret_cast<float*>(sm + 28736);

    const int tid = threadIdx.x;
    const int fg  = tid >> 3;      // 0..63: features f0, f0+1
    const int sg  = tid & 7;       // 0..7:  samples 8sg..8sg+7
    const int f0  = fg << 1;
    const int q0  = sg << 2;       // first owned sample-pair
    const int aofs = 2 * sg;       // phys u64 offset base in act/curS rows
    const int s0g = blockIdx.x * SB;

    // ---- build k-paired, chunk-swizzled weights ----
    for (int idx = tid; idx < 8192; idx += NTHR) {
        int a = idx >> 7, f = idx & 127;
        int po = a * 128 + ((((f >> 1) ^ (a & 7)) << 1) | (f & 1));
        int g = a * 256 + f;
        wp2[po] = pack2(w2[g], w2[g + 128]);
        wp3[po] = pack2(w3[g], w3[g + 128]);
        wp4[po] = pack2(w4[g], w4[g + 128]);
    }
    if (tid < 256) w1s[tid] = w1[tid];
    if (tid < 64) {
        int d = tid >> 5, s2 = tid & 31;
        size_t bx = (size_t)(s0g + 2 * s2) * 2 + d;
        xsp[tid] = pack2(x0[bx], x0[bx + 2]);
    }
    const float w1a0 = w1[f0],       w1a1 = w1[f0 + 1];
    const float w1b0 = w1[128 + f0], w1b1 = w1[128 + f0 + 1];
    const float b1c0 = b1[f0], b1c1 = b1[f0 + 1];
    const float b2c0 = b2[f0], b2c1 = b2[f0 + 1];
    const float b3c0 = b3[f0], b3c1 = b3[f0 + 1];
    const float b4c0 = b4[f0], b4c1 = b4[f0 + 1];
    const float w5c0 = w5[f0], w5c1 = w5[f0 + 1];
    __syncthreads();

    u64 sdp2[8], sdp3[8];

    // update-phase mapping
    const int jp = tid & 7;
    const int ug = tid >> 3;
    const int ud = ug >> 5;
    const int uq = ug & 31;
    // phys pair offset of logical pair uq (bwd swizzle), hoisted
    const int ucb = uq >> 1;
    const int upp = ((((ucb & 1) << 3) | (ucb >> 1)) << 1) | (uq & 1);

    for (int i = 0; i < NSTEPS; i++) {
        float eps = 10.0f * (1.0f - (float)i / 60.0f);
        float cn  = sqrtf(2.0f * eps) * 0.005f;

        float nz0 = 0.0f, nz1 = 0.0f;
        if (jp == 0) {
            size_t base = ((size_t)i * nsamp + s0g + 2 * uq) * 2 + ud;
            nz0 = noise[base];
            nz1 = noise[base + 2];
        }

        // ---- forward L1 ----
        {
            u64 wa0 = pack2(w1a0, w1a0), wa1 = pack2(w1a1, w1a1);
            u64 wb0 = pack2(w1b0, w1b0), wb1 = pack2(w1b1, w1b1);
            u64 bb0 = pack2(b1c0, b1c0), bb1 = pack2(b1c1, b1c1);
            u64 hrow[8];
#pragma unroll
            for (int q = 0; q < 4; q++) {
                u64 xa = xsp[q0 + q], xb = xsp[32 + q0 + q];
                u64 z0 = ffma2(xa, wa0, ffma2(xb, wb0, bb0));
                u64 z1 = ffma2(xa, wa1, ffma2(xb, wb1, bb1));
                u64 h0, h1, du;
                silu2(z0, h0, du);
                silu2(z1, h1, du);
                float2 a = unpack2(h0), b = unpack2(h1);
                hrow[2 * q]     = pack2(a.x, b.x);
                hrow[2 * q + 1] = pack2(a.y, b.y);
            }
#pragma unroll
            for (int c = 0; c < 4; c++) {
                ull2 st; st.x = hrow[2 * c]; st.y = hrow[2 * c + 1];
                *reinterpret_cast<ull2*>(act + fg * 64 + aofs + 16 * c) = st;
            }
        }
        __syncthreads();

        // ---- forward L2 ----
        {
            u64 acc[16];
#pragma unroll
            for (int q = 0; q < 16; q++) acc[q] = 0ULL;
            fwd_accum(wp2, act, fg, sg, acc);
            u64 hrow[8];
#pragma unroll
            for (int q = 0; q < 4; q++) {
                float2 p0e = unpack2(acc[2 * q]);
                float2 p0o = unpack2(acc[2 * q + 1]);
                float2 p1e = unpack2(acc[8 + 2 * q]);
                float2 p1o = unpack2(acc[8 + 2 * q + 1]);
                float z0e = p0e.x + p0e.y + b2c0, z0o = p0o.x + p0o.y + b2c0;
                float z1e = p1e.x + p1e.y + b2c1, z1o = p1o.x + p1o.y + b2c1;
                float h0e, d0e, h0o, d0o, h1e, d1e, h1o, d1o;
                silu_sd(z0e, h0e, d0e);  silu_sd(z0o, h0o, d0o);
                silu_sd(z1e, h1e, d1e);  silu_sd(z1o, h1o, d1o);
                hrow[2 * q]     = pack2(h0e, h1e);
                hrow[2 * q + 1] = pack2(h0o, h1o);
                sdp2[q]     = pack2(d0e, d0o);
                sdp2[4 + q] = pack2(d1e, d1o);
            }
            __syncthreads();
#pragma unroll
            for (int c = 0; c < 4; c++) {
                ull2 st; st.x = hrow[2 * c]; st.y = hrow[2 * c + 1];
                *reinterpret_cast<ull2*>(act + fg * 64 + aofs + 16 * c) = st;
            }
        }
        __syncthreads();

        // ---- forward L3 ----
        {
            u64 acc[16];
#pragma unroll
            for (int q = 0; q < 16; q++) acc[q] = 0ULL;
            fwd_accum(wp3, act, fg, sg, acc);
            u64 hrow[8];
#pragma unroll
            for (int q = 0; q < 4; q++) {
                float2 p0e = unpack2(acc[2 * q]);
                float2 p0o = unpack2(acc[2 * q + 1]);
                float2 p1e = unpack2(acc[8 + 2 * q]);
                float2 p1o = unpack2(acc[8 + 2 * q + 1]);
                float z0e = p0e.x + p0e.y + b3c0, z0o = p0o.x + p0o.y + b3c0;
                float z1e = p1e.x + p1e.y + b3c1, z1o = p1o.x + p1o.y + b3c1;
                float h0e, d0e, h0o, d0o, h1e, d1e, h1o, d1o;
                silu_sd(z0e, h0e, d0e);  silu_sd(z0o, h0o, d0o);
                silu_sd(z1e, h1e, d1e);  silu_sd(z1o, h1o, d1o);
                hrow[2 * q]     = pack2(h0e, h1e);
                hrow[2 * q + 1] = pack2(h0o, h1o);
                sdp3[q]     = pack2(d0e, d0o);
                sdp3[4 + q] = pack2(d1e, d1o);
            }
            __syncthreads();
#pragma unroll
            for (int c = 0; c < 4; c++) {
                ull2 st; st.x = hrow[2 * c]; st.y = hrow[2 * c + 1];
                *reinterpret_cast<ull2*>(act + fg * 64 + aofs + 16 * c) = st;
            }
        }
        __syncthreads();

        // ---- forward L4 + seed dz4 = w5 .* silu'(z4) (sample-paired store) ----
        {
            u64 acc[16];
#pragma unroll
            for (int q = 0; q < 16; q++) acc[q] = 0ULL;
            fwd_accum(wp4, act, fg, sg, acc);
            u64 dz0[4], dz1[4];
#pragma unroll
            for (int q = 0; q < 4; q++) {
                float2 p0e = unpack2(acc[2 * q]);
                float2 p0o = unpack2(acc[2 * q + 1]);
                float2 p1e = unpack2(acc[8 + 2 * q]);
                float2 p1o = unpack2(acc[8 + 2 * q + 1]);
                float z0e = p0e.x + p0e.y + b4c0, z0o = p0o.x + p0o.y + b4c0;
                float z1e = p1e.x + p1e.y + b4c1, z1o = p1o.x + p1o.y + b4c1;
                float h, d0e, d0o, d1e, d1o;
                silu_sd(z0e, h, d0e);  silu_sd(z0o, h, d0o);
                silu_sd(z1e, h, d1e);  silu_sd(z1o, h, d1o);
                dz0[q] = pack2(w5c0 * d0e, w5c0 * d0o);
                dz1[q] = pack2(w5c1 * d1e, w5c1 * d1o);
            }
            __syncthreads();
            {
                ull2 sa; sa.x = dz0[0]; sa.y = dz0[1];
                ull2 sb; sb.x = dz0[2]; sb.y = dz0[3];
                *reinterpret_cast<ull2*>(act + f0 * 32 + aofs)      = sa;
                *reinterpret_cast<ull2*>(act + f0 * 32 + aofs + 16) = sb;
                ull2 sc; sc.x = dz1[0]; sc.y = dz1[1];
                ull2 sd; sd.x = dz1[2]; sd.y = dz1[3];
                *reinterpret_cast<ull2*>(act + (f0 + 1) * 32 + aofs)      = sc;
                *reinterpret_cast<ull2*>(act + (f0 + 1) * 32 + aofs + 16) = sd;
            }
        }
        __syncthreads();

        // ---- backward W4 -> dz3 ----
        {
            u64 acc[8];
#pragma unroll
            for (int q = 0; q < 8; q++) acc[q] = 0ULL;
            bwd_accum(wp4, act, fg, sg, acc);
            u64 dzv[8];
#pragma unroll
            for (int q = 0; q < 8; q++) dzv[q] = fmul2(acc[q], sdp3[q]);
            __syncthreads();
            ull2 sa; sa.x = dzv[0]; sa.y = dzv[1];
            ull2 sb; sb.x = dzv[2]; sb.y = dzv[3];
            *reinterpret_cast<ull2*>(act + f0 * 32 + aofs)      = sa;
            *reinterpret_cast<ull2*>(act + f0 * 32 + aofs + 16) = sb;
            ull2 sc; sc.x = dzv[4]; sc.y = dzv[5];
            ull2 sd; sd.x = dzv[6]; sd.y = dzv[7];
            *reinterpret_cast<ull2*>(act + (f0 + 1) * 32 + aofs)      = sc;
            *reinterpret_cast<ull2*>(act + (f0 + 1) * 32 + aofs + 16) = sd;
        }
        __syncthreads();

        // ---- backward W3 -> dz2 ----
        {
            u64 acc[8];
#pragma unroll
            for (int q = 0; q < 8; q++) acc[q] = 0ULL;
            bwd_accum(wp3, act, fg, sg, acc);
            u64 dzv[8];
#pragma unroll
            for (int q = 0; q < 8; q++) dzv[q] = fmul2(acc[q], sdp2[q]);
            __syncthreads();
            ull2 sa; sa.x = dzv[0]; sa.y = dzv[1];
            ull2 sb; sb.x = dzv[2]; sb.y = dzv[3];
            *reinterpret_cast<ull2*>(act + f0 * 32 + aofs)      = sa;
            *reinterpret_cast<ull2*>(act + f0 * 32 + aofs + 16) = sb;
            ull2 sc; sc.x = dzv[4]; sc.y = dzv[5];
            ull2 sd; sd.x = dzv[6]; sd.y = dzv[7];
            *reinterpret_cast<ull2*>(act + (f0 + 1) * 32 + aofs)      = sc;
            *reinterpret_cast<ull2*>(act + (f0 + 1) * 32 + aofs + 16) = sd;
        }
        __syncthreads();

        // ---- backward W2 -> dz1 (sd1 recomputed) ----
        {
            u64 acc[8];
#pragma unroll
            for (int q = 0; q < 8; q++) acc[q] = 0ULL;
            bwd_accum(wp2, act, fg, sg, acc);
            u64 wa0 = pack2(w1a0, w1a0), wa1 = pack2(w1a1, w1a1);
            u64 wb0 = pack2(w1b0, w1b0), wb1 = pack2(w1b1, w1b1);
            u64 bb0 = pack2(b1c0, b1c0), bb1 = pack2(b1c1, b1c1);
            u64 dzv[8];
#pragma unroll
            for (int q = 0; q < 4; q++) {
                u64 xa = xsp[q0 + q], xb = xsp[32 + q0 + q];
                u64 z0 = ffma2(xa, wa0, ffma2(xb, wb0, bb0));
                u64 z1 = ffma2(xa, wa1, ffma2(xb, wb1, bb1));
                u64 h, d0, d1;
                silu2(z0, h, d0);
                silu2(z1, h, d1);
                dzv[q]     = fmul2(acc[q],     d0);
                dzv[4 + q] = fmul2(acc[4 + q], d1);
            }
            __syncthreads();
            ull2 sa; sa.x = dzv[0]; sa.y = dzv[1];
            ull2 sb; sb.x = dzv[2]; sb.y = dzv[3];
            *reinterpret_cast<ull2*>(act + f0 * 32 + aofs)      = sa;
            *reinterpret_cast<ull2*>(act + f0 * 32 + aofs + 16) = sb;
            ull2 sc; sc.x = dzv[4]; sc.y = dzv[5];
            ull2 sd; sd.x = dzv[6]; sd.y = dzv[7];
            *reinterpret_cast<ull2*>(act + (f0 + 1) * 32 + aofs)      = sc;
            *reinterpret_cast<ull2*>(act + (f0 + 1) * 32 + aofs + 16) = sd;
        }
        __syncthreads();

        // ---- g = dz1 @ W1^T, clip, Langevin update ----
        {
            u64 g = 0ULL;
#pragma unroll
            for (int jj = 0; jj < 16; jj++) {
                int j = jp * 16 + jj;
                float w = w1s[ud * 128 + j];
                g = ffma2(act[j * 32 + upp], pack2(w, w), g);
            }
            g = fadd2(g, __shfl_down_sync(0xffffffffu, g, 4, 8));
            g = fadd2(g, __shfl_down_sync(0xffffffffu, g, 2, 8));
            g = fadd2(g, __shfl_down_sync(0xffffffffu, g, 1, 8));
            if (jp == 0) {
                float2 gv = unpack2(g);
                gv.x = fminf(fmaxf(gv.x, -0.03f), 0.03f);
                gv.y = fminf(fmaxf(gv.y, -0.03f), 0.03f);
                float2 xv = unpack2(xsp[ud * 32 + uq]);
                float ax = xv.x + cn * nz0;  ax += eps * gv.x;
                float ay = xv.y + cn * nz1;  ay += eps * gv.y;
                ax = fminf(fmaxf(ax, -2.43f), 3.05f);
                ay = fminf(fmaxf(ay, -2.43f), 3.05f);
                xsp[ud * 32 + uq] = pack2(ax, ay);
            }
        }
        __syncthreads();
    }

    // ---- write final x ----
    if (tid < 128) {
        int s = tid >> 1, d = tid & 1;
        float2 v = unpack2(xsp[d * 32 + (s >> 1)]);
        out[(size_t)(s0g + s) * 2 + d] = (s & 1) ? v.y : v.x;
    }
}

extern "C" void kernel_launch(void* const* d_in, const int* in_sizes, int n_in,
                              void* d_out, int out_size) {
    const float* x0    = (const float*)d_in[0];
    const float* w1    = (const float*)d_in[1];
    const float* b1    = (const float*)d_in[2];
    const float* w2    = (const float*)d_in[3];
    const float* b2    = (const float*)d_in[4];
    const float* w3    = (const float*)d_in[5];
    const float* b3    = (const float*)d_in[6];
    const float* w4    = (const float*)d_in[7];
    const float* b4    = (const float*)d_in[8];
    const float* w5    = (const float*)d_in[9];
    const float* noise = (const float*)d_in[11];
    float* out = (float*)d_out;

    int nsamp = in_sizes[0] / 2;
    cudaFuncSetAttribute(ebm_mcmc_kernel,
                         cudaFuncAttributeMaxDynamicSharedMemorySize, SMEM_BYTES);
    int nblocks = nsamp / SB;
    ebm_mcmc_kernel<<<nblocks, NTHR, SMEM_BYTES>>>(
        x0, w1, b1, w2, b2, w3, b3, w4, b4, w5, noise, out, nsamp);
}

// round 13
// speedup vs baseline: 3.5025x; 2.2635x over previous
#include <cuda_runtime.h>

#define HDIM   128
#define NSTEPS 60
#define SB     64      // samples per block
#define NTHR   256
#define CPAD   32      // cur row length in u64 pairs

typedef unsigned long long u64;
typedef ulonglong2 ull2;

__device__ __forceinline__ u64 pack2(float a, float b) {
    u64 r; asm("mov.b64 %0, {%1, %2};" : "=l"(r) : "f"(a), "f"(b)); return r;
}
__device__ __forceinline__ float2 unpack2(u64 v) {
    float2 r; asm("mov.b64 {%0, %1}, %2;" : "=f"(r.x), "=f"(r.y) : "l"(v)); return r;
}
__device__ __forceinline__ u64 ffma2(u64 a, u64 b, u64 c) {
    u64 d; asm("fma.rn.f32x2 %0, %1, %2, %3;" : "=l"(d) : "l"(a), "l"(b), "l"(c)); return d;
}
__device__ __forceinline__ u64 fmul2(u64 a, u64 b) {
    u64 d; asm("mul.rn.f32x2 %0, %1, %2;" : "=l"(d) : "l"(a), "l"(b)); return d;
}
__device__ __forceinline__ u64 fadd2(u64 a, u64 b) {
    u64 d; asm("add.rn.f32x2 %0, %1, %2;" : "=l"(d) : "l"(a), "l"(b)); return d;
}
__device__ __forceinline__ void silu2(u64 z, u64& h, u64& d) {
    float2 zf = unpack2(z);
    float e0 = __expf(-zf.x), e1 = __expf(-zf.y);
    float s0 = 1.0f / (1.0f + e0), s1 = 1.0f / (1.0f + e1);
    float h0 = zf.x * s0,          h1 = zf.y * s1;
    float d0 = fmaf(h0, 1.0f - s0, s0);
    float d1 = fmaf(h1, 1.0f - s1, s1);
    h = pack2(h0, h1);
    d = pack2(d0, d1);
}

// Weight swizzle (same as R7): element (r,c) at float index
//   r*128 + (((c>>2) ^ (r&31)) << 2) + (c&3)

// FORWARD: acc[ff*4+ss] += sum_k W[k][f0+ff] * cur[k][pair]
// pairs: ss 0,1 -> qA,qA+1 ; ss 2,3 -> qA+16,qA+17
__device__ __forceinline__ void accum_fwd(const float* __restrict__ ws, int cc,
                                          const u64 (*__restrict__ cur)[CPAD],
                                          int qA, u64 acc[16]) {
#pragma unroll 4
    for (int k = 0; k < HDIM; k++) {
        const float4 w = *reinterpret_cast<const float4*>(
            ws + k * 128 + (((k & 31) ^ cc) << 2));
        ull2 hA = *reinterpret_cast<const ull2*>(&cur[k][qA]);
        ull2 hB = *reinterpret_cast<const ull2*>(&cur[k][qA + 16]);
        u64 wa = pack2(w.x, w.x), wb = pack2(w.y, w.y);
        u64 wc = pack2(w.z, w.z), wd = pack2(w.w, w.w);
        acc[0]  = ffma2(hA.x, wa, acc[0]);   acc[1]  = ffma2(hA.y, wa, acc[1]);
        acc[2]  = ffma2(hB.x, wa, acc[2]);   acc[3]  = ffma2(hB.y, wa, acc[3]);
        acc[4]  = ffma2(hA.x, wb, acc[4]);   acc[5]  = ffma2(hA.y, wb, acc[5]);
        acc[6]  = ffma2(hB.x, wb, acc[6]);   acc[7]  = ffma2(hB.y, wb, acc[7]);
        acc[8]  = ffma2(hA.x, wc, acc[8]);   acc[9]  = ffma2(hA.y, wc, acc[9]);
        acc[10] = ffma2(hB.x, wc, acc[10]);  acc[11] = ffma2(hB.y, wc, acc[11]);
        acc[12] = ffma2(hA.x, wd, acc[12]);  acc[13] = ffma2(hA.y, wd, acc[13]);
        acc[14] = ffma2(hB.x, wd, acc[14]);  acc[15] = ffma2(hB.y, wd, acc[15]);
    }
}

// BACKWARD: acc[ff*4+ss] += sum_k W[f0+ff][k] * cur[k][pair]
__device__ __forceinline__ void accum_bwd(const float* __restrict__ ws, int f0,
                                          const u64 (*__restrict__ cur)[CPAD],
                                          int qA, u64 acc[16]) {
    const float* r0b = ws + (f0 + 0) * 128;  const int x0m = (f0 + 0) & 31;
    const float* r1b = ws + (f0 + 1) * 128;  const int x1m = (f0 + 1) & 31;
    const float* r2b = ws + (f0 + 2) * 128;  const int x2m = (f0 + 2) & 31;
    const float* r3b = ws + (f0 + 3) * 128;  const int x3m = (f0 + 3) & 31;
#pragma unroll 4
    for (int k = 0; k < HDIM; k += 4) {
        int cc = k >> 2;
        float4 w0 = *reinterpret_cast<const float4*>(r0b + ((cc ^ x0m) << 2));
        float4 w1 = *reinterpret_cast<const float4*>(r1b + ((cc ^ x1m) << 2));
        float4 w2 = *reinterpret_cast<const float4*>(r2b + ((cc ^ x2m) << 2));
        float4 w3 = *reinterpret_cast<const float4*>(r3b + ((cc ^ x3m) << 2));
        ull2 hA0 = *reinterpret_cast<const ull2*>(&cur[k + 0][qA]);
        ull2 hA1 = *reinterpret_cast<const ull2*>(&cur[k + 1][qA]);
        ull2 hA2 = *reinterpret_cast<const ull2*>(&cur[k + 2][qA]);
        ull2 hA3 = *reinterpret_cast<const ull2*>(&cur[k + 3][qA]);
        ull2 hB0 = *reinterpret_cast<const ull2*>(&cur[k + 0][qA + 16]);
        ull2 hB1 = *reinterpret_cast<const ull2*>(&cur[k + 1][qA + 16]);
        ull2 hB2 = *reinterpret_cast<const ull2*>(&cur[k + 2][qA + 16]);
        ull2 hB3 = *reinterpret_cast<const ull2*>(&cur[k + 3][qA + 16]);

        u64 t;
        t = pack2(w0.x, w0.x);
        acc[0] = ffma2(hA0.x, t, acc[0]);  acc[1] = ffma2(hA0.y, t, acc[1]);
        acc[2] = ffma2(hB0.x, t, acc[2]);  acc[3] = ffma2(hB0.y, t, acc[3]);
        t = pack2(w0.y, w0.y);
        acc[0] = ffma2(hA1.x, t, acc[0]);  acc[1] = ffma2(hA1.y, t, acc[1]);
        acc[2] = ffma2(hB1.x, t, acc[2]);  acc[3] = ffma2(hB1.y, t, acc[3]);
        t = pack2(w0.z, w0.z);
        acc[0] = ffma2(hA2.x, t, acc[0]);  acc[1] = ffma2(hA2.y, t, acc[1]);
        acc[2] = ffma2(hB2.x, t, acc[2]);  acc[3] = ffma2(hB2.y, t, acc[3]);
        t = pack2(w0.w, w0.w);
        acc[0] = ffma2(hA3.x, t, acc[0]);  acc[1] = ffma2(hA3.y, t, acc[1]);
        acc[2] = ffma2(hB3.x, t, acc[2]);  acc[3] = ffma2(hB3.y, t, acc[3]);

        t = pack2(w1.x, w1.x);
        acc[4] = ffma2(hA0.x, t, acc[4]);  acc[5] = ffma2(hA0.y, t, acc[5]);
        acc[6] = ffma2(hB0.x, t, acc[6]);  acc[7] = ffma2(hB0.y, t, acc[7]);
        t = pack2(w1.y, w1.y);
        acc[4] = ffma2(hA1.x, t, acc[4]);  acc[5] = ffma2(hA1.y, t, acc[5]);
        acc[6] = ffma2(hB1.x, t, acc[6]);  acc[7] = ffma2(hB1.y, t, acc[7]);
        t = pack2(w1.z, w1.z);
        acc[4] = ffma2(hA2.x, t, acc[4]);  acc[5] = ffma2(hA2.y, t, acc[5]);
        acc[6] = ffma2(hB2.x, t, acc[6]);  acc[7] = ffma2(hB2.y, t, acc[7]);
        t = pack2(w1.w, w1.w);
        acc[4] = ffma2(hA3.x, t, acc[4]);  acc[5] = ffma2(hA3.y, t, acc[5]);
        acc[6] = ffma2(hB3.x, t, acc[6]);  acc[7] = ffma2(hB3.y, t, acc[7]);

        t = pack2(w2.x, w2.x);
        acc[8]  = ffma2(hA0.x, t, acc[8]);   acc[9]  = ffma2(hA0.y, t, acc[9]);
        acc[10] = ffma2(hB0.x, t, acc[10]);  acc[11] = ffma2(hB0.y, t, acc[11]);
        t = pack2(w2.y, w2.y);
        acc[8]  = ffma2(hA1.x, t, acc[8]);   acc[9]  = ffma2(hA1.y, t, acc[9]);
        acc[10] = ffma2(hB1.x, t, acc[10]);  acc[11] = ffma2(hB1.y, t, acc[11]);
        t = pack2(w2.z, w2.z);
        acc[8]  = ffma2(hA2.x, t, acc[8]);   acc[9]  = ffma2(hA2.y, t, acc[9]);
        acc[10] = ffma2(hB2.x, t, acc[10]);  acc[11] = ffma2(hB2.y, t, acc[11]);
        t = pack2(w2.w, w2.w);
        acc[8]  = ffma2(hA3.x, t, acc[8]);   acc[9]  = ffma2(hA3.y, t, acc[9]);
        acc[10] = ffma2(hB3.x, t, acc[10]);  acc[11] = ffma2(hB3.y, t, acc[11]);

        t = pack2(w3.x, w3.x);
        acc[12] = ffma2(hA0.x, t, acc[12]);  acc[13] = ffma2(hA0.y, t, acc[13]);
        acc[14] = ffma2(hB0.x, t, acc[14]);  acc[15] = ffma2(hB0.y, t, acc[15]);
        t = pack2(w3.y, w3.y);
        acc[12] = ffma2(hA1.x, t, acc[12]);  acc[13] = ffma2(hA1.y, t, acc[13]);
        acc[14] = ffma2(hB1.x, t, acc[14]);  acc[15] = ffma2(hB1.y, t, acc[15]);
        t = pack2(w3.z, w3.z);
        acc[12] = ffma2(hA2.x, t, acc[12]);  acc[13] = ffma2(hA2.y, t, acc[13]);
        acc[14] = ffma2(hB2.x, t, acc[14]);  acc[15] = ffma2(hB2.y, t, acc[15]);
        t = pack2(w3.w, w3.w);
        acc[12] = ffma2(hA3.x, t, acc[12]);  acc[13] = ffma2(hA3.y, t, acc[13]);
        acc[14] = ffma2(hB3.x, t, acc[14]);  acc[15] = ffma2(hB3.y, t, acc[15]);
    }
}

// SMEM layout (bytes) — identical to R7:
//   cur 0 (32768) | w2s 32768 | w3s 98304 | w4s 163840 | w1s 229376 (1024)
//   b2s 230400 | b3s 230912 | b4s 231424 | xs 231936 (512)
#define SMEM_BYTES 232448

__global__ void __launch_bounds__(NTHR, 1)
ebm_mcmc_kernel(const float* __restrict__ x0,
                const float* __restrict__ w1, const float* __restrict__ b1,
                const float* __restrict__ w2, const float* __restrict__ b2,
                const float* __restrict__ w3, const float* __restrict__ b3,
                const float* __restrict__ w4, const float* __restrict__ b4,
                const float* __restrict__ w5,
                const float* __restrict__ noise,
                float* __restrict__ out, int nsamp) {
    extern __shared__ unsigned char smraw[];
    u64 (*cur)[CPAD] = reinterpret_cast<u64(*)[CPAD]>(smraw);
    float* w2s = reinterpret_cast<float*>(smraw + 32768);
    float* w3s = w2s + HDIM * 128;
    float* w4s = w3s + HDIM * 128;
    float* w1s = w4s + HDIM * 128;    // [2][128]
    float* b2s = w1s + 256;
    float* b3s = b2s + 128;
    float* b4s = b3s + 128;
    u64*   xs  = reinterpret_cast<u64*>(b4s + 128);   // xs[d*32 + pair]

    const int tid = threadIdx.x;
    const int f0  = (tid >> 3) * 4;   // 4 contiguous output features
    const int cc0 = f0 >> 2;
    const int qA  = (tid & 7) * 2;    // pairs qA,qA+1 and qA+16,qA+17
    const int s0  = blockIdx.x * SB;

    // ---- load weights into SMEM (swizzled), once per block ----
    for (int idx = tid; idx < HDIM * HDIM; idx += NTHR) {
        int r = idx >> 7, c = idx & 127;
        int o = r * 128 + ((((c >> 2) ^ (r & 31)) << 2) | (c & 3));
        w2s[o] = w2[idx];
        w3s[o] = w3[idx];
        w4s[o] = w4[idx];
    }
    w1s[tid] = w1[tid];
    if (tid < 128) {
        b2s[tid] = b2[tid];
        b3s[tid] = b3[tid];
        b4s[tid] = b4[tid];
    }
    if (tid < 64) {
        int d = tid >> 5, p = tid & 31;
        size_t bx = (size_t)(s0 + 2 * p) * 2 + d;
        xs[tid] = pack2(x0[bx], x0[bx + 2]);
    }
    const float4 b1r = *reinterpret_cast<const float4*>(b1 + f0);
    const float4 w5r = *reinterpret_cast<const float4*>(w5 + f0);
    __syncthreads();

    // silu' (16 pairs each = 4f x 4 sample-pairs); sd1 recomputed; sd4 transient
    u64 sd2[16], sd3[16];

    // update-phase mapping: jp width 4 (32 j each)
    const int jp = tid & 3;
    const int ug = tid >> 2;       // 0..63
    const int ud = ug >> 5;        // dim
    const int uq = ug & 31;        // pair

    for (int i = 0; i < NSTEPS; i++) {
        float eps = 10.0f * (1.0f - (float)i / 60.0f);
        float cn  = sqrtf(2.0f * eps) * 0.005f;

        float nz0 = 0.0f, nz1 = 0.0f;
        if (jp == 0) {
            size_t base = ((size_t)i * nsamp + s0 + 2 * uq) * 2 + ud;
            nz0 = noise[base];
            nz1 = noise[base + 2];
        }

        // ---- forward L1 ----
        {
            float4 wa = *reinterpret_cast<const float4*>(w1s + f0);
            float4 wb = *reinterpret_cast<const float4*>(w1s + 128 + f0);
            u64 xA0 = xs[qA],      xA1 = xs[qA + 1];
            u64 xB0 = xs[qA + 16], xB1 = xs[qA + 17];
            u64 yA0 = xs[32 + qA],      yA1 = xs[32 + qA + 1];
            u64 yB0 = xs[32 + qA + 16], yB1 = xs[32 + qA + 17];
            float wav[4] = {wa.x, wa.y, wa.z, wa.w};
            float wbv[4] = {wb.x, wb.y, wb.z, wb.w};
            float bbv[4] = {b1r.x, b1r.y, b1r.z, b1r.w};
#pragma unroll
            for (int ff = 0; ff < 4; ff++) {
                u64 wap = pack2(wav[ff], wav[ff]);
                u64 wbp = pack2(wbv[ff], wbv[ff]);
                u64 bbp = pack2(bbv[ff], bbv[ff]);
                u64 zA0 = ffma2(xA0, wap, ffma2(yA0, wbp, bbp));
                u64 zA1 = ffma2(xA1, wap, ffma2(yA1, wbp, bbp));
                u64 zB0 = ffma2(xB0, wap, ffma2(yB0, wbp, bbp));
                u64 zB1 = ffma2(xB1, wap, ffma2(yB1, wbp, bbp));
                u64 hA0, hA1, hB0, hB1, du;
                silu2(zA0, hA0, du);  silu2(zA1, hA1, du);
                silu2(zB0, hB0, du);  silu2(zB1, hB1, du);
                ull2 sa; sa.x = hA0; sa.y = hA1;
                ull2 sb; sb.x = hB0; sb.y = hB1;
                *reinterpret_cast<ull2*>(&cur[f0 + ff][qA])      = sa;
                *reinterpret_cast<ull2*>(&cur[f0 + ff][qA + 16]) = sb;
            }
        }
        __syncthreads();

        // ---- forward L2 ----
        {
            u64 acc[16];
            float4 bb = *reinterpret_cast<const float4*>(b2s + f0);
            float bbv[4] = {bb.x, bb.y, bb.z, bb.w};
#pragma unroll
            for (int ff = 0; ff < 4; ff++) {
                u64 bp = pack2(bbv[ff], bbv[ff]);
                acc[4 * ff] = acc[4 * ff + 1] = acc[4 * ff + 2] = acc[4 * ff + 3] = bp;
            }
            accum_fwd(w2s, cc0, cur, qA, acc);
            __syncthreads();
#pragma unroll
            for (int ff = 0; ff < 4; ff++) {
                u64 hA0, hA1, hB0, hB1;
                silu2(acc[4 * ff],     hA0, sd2[4 * ff]);
                silu2(acc[4 * ff + 1], hA1, sd2[4 * ff + 1]);
                silu2(acc[4 * ff + 2], hB0, sd2[4 * ff + 2]);
                silu2(acc[4 * ff + 3], hB1, sd2[4 * ff + 3]);
                ull2 sa; sa.x = hA0; sa.y = hA1;
                ull2 sb; sb.x = hB0; sb.y = hB1;
                *reinterpret_cast<ull2*>(&cur[f0 + ff][qA])      = sa;
                *reinterpret_cast<ull2*>(&cur[f0 + ff][qA + 16]) = sb;
            }
        }
        __syncthreads();

        // ---- forward L3 ----
        {
            u64 acc[16];
            float4 bb = *reinterpret_cast<const float4*>(b3s + f0);
            float bbv[4] = {bb.x, bb.y, bb.z, bb.w};
#pragma unroll
            for (int ff = 0; ff < 4; ff++) {
                u64 bp = pack2(bbv[ff], bbv[ff]);
                acc[4 * ff] = acc[4 * ff + 1] = acc[4 * ff + 2] = acc[4 * ff + 3] = bp;
            }
            accum_fwd(w3s, cc0, cur, qA, acc);
            __syncthreads();
#pragma unroll
            for (int ff = 0; ff < 4; ff++) {
                u64 hA0, hA1, hB0, hB1;
                silu2(acc[4 * ff],     hA0, sd3[4 * ff]);
                silu2(acc[4 * ff + 1], hA1, sd3[4 * ff + 1]);
                silu2(acc[4 * ff + 2], hB0, sd3[4 * ff + 2]);
                silu2(acc[4 * ff + 3], hB1, sd3[4 * ff + 3]);
                ull2 sa; sa.x = hA0; sa.y = hA1;
                ull2 sb; sb.x = hB0; sb.y = hB1;
                *reinterpret_cast<ull2*>(&cur[f0 + ff][qA])      = sa;
                *reinterpret_cast<ull2*>(&cur[f0 + ff][qA + 16]) = sb;
            }
        }
        __syncthreads();

        // ---- forward L4 (h4 dead) + seed dz4 = w5 .* silu'(z4) ----
        {
            u64 acc[16];
            float4 bb = *reinterpret_cast<const float4*>(b4s + f0);
            float bbv[4] = {bb.x, bb.y, bb.z, bb.w};
#pragma unroll
            for (int ff = 0; ff < 4; ff++) {
                u64 bp = pack2(bbv[ff], bbv[ff]);
                acc[4 * ff] = acc[4 * ff + 1] = acc[4 * ff + 2] = acc[4 * ff + 3] = bp;
            }
            accum_fwd(w4s, cc0, cur, qA, acc);
            float w5a[4] = {w5r.x, w5r.y, w5r.z, w5r.w};
            u64 dz[16];
#pragma unroll
            for (int ff = 0; ff < 4; ff++) {
                u64 h, d0, d1, d2, d3;
                silu2(acc[4 * ff],     h, d0);
                silu2(acc[4 * ff + 1], h, d1);
                silu2(acc[4 * ff + 2], h, d2);
                silu2(acc[4 * ff + 3], h, d3);
                u64 wp = pack2(w5a[ff], w5a[ff]);
                dz[4 * ff]     = fmul2(wp, d0);
                dz[4 * ff + 1] = fmul2(wp, d1);
                dz[4 * ff + 2] = fmul2(wp, d2);
                dz[4 * ff + 3] = fmul2(wp, d3);
            }
            __syncthreads();   // all reads of h3 done
#pragma unroll
            for (int ff = 0; ff < 4; ff++) {
                ull2 sa; sa.x = dz[4 * ff];     sa.y = dz[4 * ff + 1];
                ull2 sb; sb.x = dz[4 * ff + 2]; sb.y = dz[4 * ff + 3];
                *reinterpret_cast<ull2*>(&cur[f0 + ff][qA])      = sa;
                *reinterpret_cast<ull2*>(&cur[f0 + ff][qA + 16]) = sb;
            }
        }
        __syncthreads();

        // ---- backward W4 -> dz3 ----
        {
            u64 acc[16];
#pragma unroll
            for (int q = 0; q < 16; q++) acc[q] = 0ULL;
            accum_bwd(w4s, f0, cur, qA, acc);
            __syncthreads();
#pragma unroll
            for (int ff = 0; ff < 4; ff++) {
                ull2 sa, sb;
                sa.x = fmul2(acc[4 * ff],     sd3[4 * ff]);
                sa.y = fmul2(acc[4 * ff + 1], sd3[4 * ff + 1]);
                sb.x = fmul2(acc[4 * ff + 2], sd3[4 * ff + 2]);
                sb.y = fmul2(acc[4 * ff + 3], sd3[4 * ff + 3]);
                *reinterpret_cast<ull2*>(&cur[f0 + ff][qA])      = sa;
                *reinterpret_cast<ull2*>(&cur[f0 + ff][qA + 16]) = sb;
            }
        }
        __syncthreads();

        // ---- backward W3 -> dz2 ----
        {
            u64 acc[16];
#pragma unroll
            for (int q = 0; q < 16; q++) acc[q] = 0ULL;
            accum_bwd(w3s, f0, cur, qA, acc);
            __syncthreads();
#pragma unroll
            for (int ff = 0; ff < 4; ff++) {
                ull2 sa, sb;
                sa.x = fmul2(acc[4 * ff],     sd2[4 * ff]);
                sa.y = fmul2(acc[4 * ff + 1], sd2[4 * ff + 1]);
                sb.x = fmul2(acc[4 * ff + 2], sd2[4 * ff + 2]);
                sb.y = fmul2(acc[4 * ff + 3], sd2[4 * ff + 3]);
                *reinterpret_cast<ull2*>(&cur[f0 + ff][qA])      = sa;
                *reinterpret_cast<ull2*>(&cur[f0 + ff][qA + 16]) = sb;
            }
        }
        __syncthreads();

        // ---- backward W2 -> dz1 (sd1 recomputed) ----
        {
            u64 acc[16];
#pragma unroll
            for (int q = 0; q < 16; q++) acc[q] = 0ULL;
            accum_bwd(w2s, f0, cur, qA, acc);
            float4 wa = *reinterpret_cast<const float4*>(w1s + f0);
            float4 wb = *reinterpret_cast<const float4*>(w1s + 128 + f0);
            u64 xA0 = xs[qA],      xA1 = xs[qA + 1];
            u64 xB0 = xs[qA + 16], xB1 = xs[qA + 17];
            u64 yA0 = xs[32 + qA],      yA1 = xs[32 + qA + 1];
            u64 yB0 = xs[32 + qA + 16], yB1 = xs[32 + qA + 17];
            float wav[4] = {wa.x, wa.y, wa.z, wa.w};
            float wbv[4] = {wb.x, wb.y, wb.z, wb.w};
            float bbv[4] = {b1r.x, b1r.y, b1r.z, b1r.w};
            u64 dzv[16];
#pragma unroll
            for (int ff = 0; ff < 4; ff++) {
                u64 wap = pack2(wav[ff], wav[ff]);
                u64 wbp = pack2(wbv[ff], wbv[ff]);
                u64 bbp = pack2(bbv[ff], bbv[ff]);
                u64 zA0 = ffma2(xA0, wap, ffma2(yA0, wbp, bbp));
                u64 zA1 = ffma2(xA1, wap, ffma2(yA1, wbp, bbp));
                u64 zB0 = ffma2(xB0, wap, ffma2(yB0, wbp, bbp));
                u64 zB1 = ffma2(xB1, wap, ffma2(yB1, wbp, bbp));
                u64 h, d0, d1, d2, d3;
                silu2(zA0, h, d0);  silu2(zA1, h, d1);
                silu2(zB0, h, d2);  silu2(zB1, h, d3);
                dzv[4 * ff]     = fmul2(acc[4 * ff],     d0);
                dzv[4 * ff + 1] = fmul2(acc[4 * ff + 1], d1);
                dzv[4 * ff + 2] = fmul2(acc[4 * ff + 2], d2);
                dzv[4 * ff + 3] = fmul2(acc[4 * ff + 3], d3);
            }
            __syncthreads();
#pragma unroll
            for (int ff = 0; ff < 4; ff++) {
                ull2 sa; sa.x = dzv[4 * ff];     sa.y = dzv[4 * ff + 1];
                ull2 sb; sb.x = dzv[4 * ff + 2]; sb.y = dzv[4 * ff + 3];
                *reinterpret_cast<ull2*>(&cur[f0 + ff][qA])      = sa;
                *reinterpret_cast<ull2*>(&cur[f0 + ff][qA + 16]) = sb;
            }
        }
        __syncthreads();

        // ---- g = dz1 @ W1^T, clip, Langevin update ----
        {
            u64 g = 0ULL;
#pragma unroll
            for (int jj = 0; jj < 32; jj++) {
                int j = jp * 32 + jj;
                float w = w1s[ud * 128 + j];
                g = ffma2(cur[j][uq], pack2(w, w), g);
            }
            g = fadd2(g, __shfl_down_sync(0xffffffffu, g, 2, 4));
            g = fadd2(g, __shfl_down_sync(0xffffffffu, g, 1, 4));
            if (jp == 0) {
                float2 gv = unpack2(g);
                gv.x = fminf(fmaxf(gv.x, -0.03f), 0.03f);
                gv.y = fminf(fmaxf(gv.y, -0.03f), 0.03f);
                float2 xv = unpack2(xs[ud * 32 + uq]);
                float ax = xv.x + cn * nz0;  ax += eps * gv.x;
                float ay = xv.y + cn * nz1;  ay += eps * gv.y;
                ax = fminf(fmaxf(ax, -2.43f), 3.05f);
                ay = fminf(fmaxf(ay, -2.43f), 3.05f);
                xs[ud * 32 + uq] = pack2(ax, ay);
            }
        }
        __syncthreads();
    }

    // ---- write final x ----
    if (tid < 128) {
        int s = tid >> 1, d = tid & 1;
        float2 v = unpack2(xs[d * 32 + (s >> 1)]);
        out[(size_t)(s0 + s) * 2 + d] = (s & 1) ? v.y : v.x;
    }
}

extern "C" void kernel_launch(void* const* d_in, const int* in_sizes, int n_in,
                              void* d_out, int out_size) {
    const float* x0    = (const float*)d_in[0];
    const float* w1    = (const float*)d_in[1];
    const float* b1    = (const float*)d_in[2];
    const float* w2    = (const float*)d_in[3];
    const float* b2    = (const float*)d_in[4];
    const float* w3    = (const float*)d_in[5];
    const float* b3    = (const float*)d_in[6];
    const float* w4    = (const float*)d_in[7];
    const float* b4    = (const float*)d_in[8];
    const float* w5    = (const float*)d_in[9];
    const float* noise = (const float*)d_in[11];
    float* out = (float*)d_out;

    int nsamp = in_sizes[0] / 2;
    cudaFuncSetAttribute(ebm_mcmc_kernel,
                         cudaFuncAttributeMaxDynamicSharedMemorySize, SMEM_BYTES);
    int nblocks = nsamp / SB;
    ebm_mcmc_kernel<<<nblocks, NTHR, SMEM_BYTES>>>(
        x0, w1, b1, w2, b2, w3, b3, w4, b4, w5, noise, out, nsamp);
}